// round 9
// baseline (speedup 1.0000x reference)
#include <cuda_runtime.h>
#include <cuda_bf16.h>
#include <cstdint>

#define NN 100000
#define EE 100000
#define D  128
#define LDP 1920
#define NSLOT 67

#define WPAD   272                 // bytes per padded row (136 bf16)
#define WPLANE (128 * WPAD)        // 34816 B: one 128x128 bf16 plane
#define WSLOT  (2 * WPLANE)        // hi + lo planes per weight matrix
#define BPLANE (64 * WPAD)         // 17408 B: 64-row half of a weight plane

// ---------------- device scratch (no mallocs allowed) ----------------
__device__ float g_feat[NN * D];          // 51.2 MB
__device__ float g_h   [NN * D];          // 51.2 MB
__device__ float g_h2  [NN * D];          // 51.2 MB
__device__ float g_q   [NN * D];          // 51.2 MB
__device__ float g_P   [NN * LDP];        // 768 MB: [ctr(128) | 14 x edge msgs(128)]
__device__ __align__(16) unsigned char g_wb[NSLOT * WSLOT];   // 4.7 MB padded hi/lo bf16 weights

// ---------------- PTX helpers (baseline ISA only — no 'a'-gated features) ----------------
__device__ __forceinline__ uint32_t smem_u32(const void* p) {
    uint32_t a;
    asm("{ .reg .u64 t; cvta.to.shared.u64 t, %1; cvt.u32.u64 %0, t; }" : "=r"(a) : "l"(p));
    return a;
}
#define LDSM4(r, addr) \
    asm volatile("ldmatrix.sync.aligned.m8n8.x4.shared.b16 {%0,%1,%2,%3}, [%4];" \
                 : "=r"((r)[0]), "=r"((r)[1]), "=r"((r)[2]), "=r"((r)[3]) : "r"(addr))
#define MMA_BF16(d, a, b0, b1) \
    asm volatile("mma.sync.aligned.m16n8k16.row.col.f32.bf16.bf16.f32 " \
                 "{%0,%1,%2,%3}, {%4,%5,%6,%7}, {%8,%9}, {%0,%1,%2,%3};" \
                 : "+f"((d)[0]), "+f"((d)[1]), "+f"((d)[2]), "+f"((d)[3]) \
                 : "r"((a)[0]), "r"((a)[1]), "r"((a)[2]), "r"((a)[3]), "r"(b0), "r"(b1))

// ---------------- weight conversion: fp32 -> hi/lo bf16, padded layout ----------------
// slots: 0 in2_W, 1 seg2_W, 2 meta_W[:, :128] (ld 132), 3..6 ctr_W, 7..10 ctr2_W, 11..66 edge_W
__global__ __launch_bounds__(256) void convert_w_k(
    const float* __restrict__ in2_W, const float* __restrict__ seg2_W,
    const float* __restrict__ meta_W, const float* __restrict__ ctr_W,
    const float* __restrict__ ctr2_W, const float* __restrict__ edge_W)
{
    int b = blockIdx.x;
    const float* src;
    int ld = 128;
    if      (b == 0) src = in2_W;
    else if (b == 1) src = seg2_W;
    else if (b == 2) { src = meta_W; ld = 132; }
    else if (b < 7)  src = ctr_W  + (long long)(b - 3) * 16384;
    else if (b < 11) src = ctr2_W + (long long)(b - 7) * 16384;
    else             src = edge_W + (long long)(b - 11) * 16384;
    unsigned char* base = g_wb + (size_t)b * WSLOT;
    for (int idx = threadIdx.x; idx < 16384; idx += 256) {
        int row = idx >> 7, col = idx & 127;      // row = output channel j, col = k
        float x = src[(long long)row * ld + col];
        __nv_bfloat16 h = __float2bfloat16_rn(x);
        __nv_bfloat16 l = __float2bfloat16_rn(x - __bfloat162float(h));
        *(__nv_bfloat16*)(base + row * WPAD + col * 2)          = h;
        *(__nv_bfloat16*)(base + WPLANE + row * WPAD + col * 2) = l;
    }
}

// ---------------- tensor-core GEMM: C[r, coly+j] = sum_k A[r,k] * W[j,k] ----------------
// split-bf16 3-term (Ahi*Bhi + Ahi*Blo + Alo*Bhi) via mma.sync m16n8k16, fp32 accum.
// 128m x 64n CTA tile, K=128 staged once, 8 warps (4m x 2n), warp tile 32x32.
// smem 102 KB -> 2 CTAs/SM: one CTA's staging phase is covered by the other's mainloop.
// grid.y enumerates 64-col half-tiles: slot = slot0 + y/2, B rows 64*(y&1).., coly = coly0 + 64*y.
#define S_AHI 0
#define S_ALO WPLANE
#define S_BHI (2 * WPLANE)
#define S_BLO (2 * WPLANE + BPLANE)
#define S_TOTAL (2 * WPLANE + 2 * BPLANE)   // 104448 B

__global__ __launch_bounds__(256, 1)
void gemm_tc(const float* __restrict__ A, int lda, int slot0,
             float* __restrict__ C, int ldc, int coly0, int nrows)
{
    extern __shared__ char smem[];
    const uint32_t sb = smem_u32(smem);
    const int tid = threadIdx.x, lane = tid & 31, wid = tid >> 5;
    const int m0   = blockIdx.x * 128;
    const int slot = slot0 + (blockIdx.y >> 1);
    const int half = blockIdx.y & 1;
    const int coly = coly0 + blockIdx.y * 64;

    // B: copy this half's 64 rows of hi and lo planes (17 KB each)
    {
        const uint4* shi = (const uint4*)(g_wb + (size_t)slot * WSLOT + (size_t)half * BPLANE);
        const uint4* slo = (const uint4*)(g_wb + (size_t)slot * WSLOT + WPLANE + (size_t)half * BPLANE);
        uint4* dhi = (uint4*)(smem + S_BHI);
        uint4* dlo = (uint4*)(smem + S_BLO);
        for (int i = tid; i < BPLANE / 16; i += 256) { dhi[i] = shi[i]; dlo[i] = slo[i]; }
    }
    // A: load fp32, split hi/lo bf16, store padded
    for (int i = tid; i < 4096; i += 256) {
        int row = i >> 5, c0 = (i & 31) * 4;
        float4 v = make_float4(0.f, 0.f, 0.f, 0.f);
        int gr = m0 + row;
        if (gr < nrows) v = *(const float4*)(A + (size_t)gr * lda + c0);
        float xs[4] = {v.x, v.y, v.z, v.w};
        uint32_t hw[2], lw[2];
#pragma unroll
        for (int j = 0; j < 2; j++) {
            __nv_bfloat16 h0 = __float2bfloat16_rn(xs[2 * j]);
            __nv_bfloat16 h1 = __float2bfloat16_rn(xs[2 * j + 1]);
            __nv_bfloat16 l0 = __float2bfloat16_rn(xs[2 * j] - __bfloat162float(h0));
            __nv_bfloat16 l1 = __float2bfloat16_rn(xs[2 * j + 1] - __bfloat162float(h1));
            hw[j] = (uint32_t)__bfloat16_as_ushort(h0) | ((uint32_t)__bfloat16_as_ushort(h1) << 16);
            lw[j] = (uint32_t)__bfloat16_as_ushort(l0) | ((uint32_t)__bfloat16_as_ushort(l1) << 16);
        }
        *(uint2*)(smem + S_AHI + row * WPAD + c0 * 2) = make_uint2(hw[0], hw[1]);
        *(uint2*)(smem + S_ALO + row * WPAD + c0 * 2) = make_uint2(lw[0], lw[1]);
    }
    __syncthreads();

    const int wm = (wid & 3) * 32;       // warp m offset (4 warps in m)
    const int wn = (wid >> 2) * 32;      // warp n offset (2 warps in n)
    float acc[2][4][4];
#pragma unroll
    for (int a = 0; a < 2; a++)
#pragma unroll
        for (int b = 0; b < 4; b++) { acc[a][b][0] = acc[a][b][1] = acc[a][b][2] = acc[a][b][3] = 0.f; }

    // ldmatrix lane addressing (x4): A rows m..m+15 (k0 | k0+8), B rows n..n+15 likewise
    const int arow = lane & 15, ak = (lane >> 4) * 8;
    const int brow = ((lane >> 4) << 3) + (lane & 7), bk = ((lane >> 3) & 1) * 8;

#pragma unroll
    for (int ks = 0; ks < 8; ks++) {
        int k0 = ks * 16;
        uint32_t ah[2][4], al[2][4], bh[2][4], bl[2][4];
#pragma unroll
        for (int mi = 0; mi < 2; mi++) {
            uint32_t ad = sb + S_AHI + (wm + mi * 16 + arow) * WPAD + (k0 + ak) * 2;
            LDSM4(ah[mi], ad);
            LDSM4(al[mi], ad + WPLANE);
        }
#pragma unroll
        for (int np = 0; np < 2; np++) {
            uint32_t bd = sb + S_BHI + (wn + np * 16 + brow) * WPAD + (k0 + bk) * 2;
            LDSM4(bh[np], bd);
            LDSM4(bl[np], bd + BPLANE);
        }
#pragma unroll
        for (int mi = 0; mi < 2; mi++)
#pragma unroll
            for (int ni = 0; ni < 4; ni++) {
                int np = ni >> 1, hh = (ni & 1) * 2;
                MMA_BF16(acc[mi][ni], ah[mi], bh[np][hh], bh[np][hh + 1]);
                MMA_BF16(acc[mi][ni], ah[mi], bl[np][hh], bl[np][hh + 1]);
                MMA_BF16(acc[mi][ni], al[mi], bh[np][hh], bh[np][hh + 1]);
            }
    }

    // epilogue: D frag -> gmem (float2 per thread per frag-half)
    const int r0 = lane >> 2, cq = (lane & 3) * 2;
#pragma unroll
    for (int mi = 0; mi < 2; mi++) {
        int gm = m0 + wm + mi * 16 + r0;
#pragma unroll
        for (int ni = 0; ni < 4; ni++) {
            float* cp = C + (size_t)gm * ldc + coly + wn + ni * 8 + cq;
            if (gm < nrows)     *(float2*)cp = make_float2(acc[mi][ni][0], acc[mi][ni][1]);
            if (gm + 8 < nrows) *(float2*)(cp + (size_t)8 * ldc) = make_float2(acc[mi][ni][2], acc[mi][ni][3]);
        }
    }
}

// ---------------- scatter: P[dst, 0:128] += P[src, 128 + 128*t : ...] ----------------
__global__ __launch_bounds__(256) void scatter_k(
    const int* __restrict__ idx, const int* __restrict__ mask,
    float* __restrict__ P, int ne)
{
    int gw   = (blockIdx.x * blockDim.x + threadIdx.x) >> 5;
    int lane = threadIdx.x & 31;
    if (gw >= 14 * ne) return;
    int t = gw / ne;
    int e = gw - t * ne;
    if (e >= __ldg(&mask[t])) return;
    int dst = __ldg(&idx[e * 28 + 2 * t]);
    int src = __ldg(&idx[e * 28 + 2 * t + 1]);
    float4 v = *(const float4*)(P + (long long)src * LDP + 128 + t * 128 + lane * 4);
    float* p = P + (long long)dst * LDP + lane * 4;
    asm volatile("red.global.add.v4.f32 [%0], {%1,%2,%3,%4};"
                 :: "l"(p), "f"(v.x), "f"(v.y), "f"(v.z), "f"(v.w) : "memory");
}

// ---------------- GroupNorm(1 group): 1 warp per row of 128 ----------------
__device__ __forceinline__ void gn_stats(float s1, float s2, float& mean, float& inv)
{
#pragma unroll
    for (int o = 16; o > 0; o >>= 1) {
        s1 += __shfl_xor_sync(0xffffffffu, s1, o);
        s2 += __shfl_xor_sync(0xffffffffu, s2, o);
    }
    mean = s1 * (1.f / 128.f);
    float var = s2 * (1.f / 128.f) - mean * mean;
    inv = rsqrtf(var + 1e-5f);
}

__global__ __launch_bounds__(256) void gn_relu_k(
    const float* __restrict__ X, int ldx,
    const float* __restrict__ g, const float* __restrict__ b,
    float* __restrict__ out, int n)
{
    int gt = blockIdx.x * blockDim.x + threadIdx.x;
    int row = gt >> 5, lane = gt & 31;
    if (row >= n) return;
    float4 v = *(const float4*)(X + (long long)row * ldx + lane * 4);
    float m, inv;
    gn_stats(v.x + v.y + v.z + v.w, v.x * v.x + v.y * v.y + v.z * v.z + v.w * v.w, m, inv);
    float4 gg = *(const float4*)(g + lane * 4);
    float4 bb = *(const float4*)(b + lane * 4);
    float4 o;
    o.x = fmaxf((v.x - m) * inv * gg.x + bb.x, 0.f);
    o.y = fmaxf((v.y - m) * inv * gg.y + bb.y, 0.f);
    o.z = fmaxf((v.z - m) * inv * gg.z + bb.z, 0.f);
    o.w = fmaxf((v.w - m) * inv * gg.w + bb.w, 0.f);
    *(float4*)(out + (long long)row * 128 + lane * 4) = o;
}

__global__ __launch_bounds__(256) void gn_add_relu_k(
    const float* __restrict__ Q,
    const float* __restrict__ g, const float* __restrict__ b,
    float* __restrict__ feat, int n)
{
    int gt = blockIdx.x * blockDim.x + threadIdx.x;
    int row = gt >> 5, lane = gt & 31;
    if (row >= n) return;
    float4 v = *(const float4*)(Q + (long long)row * 128 + lane * 4);
    float m, inv;
    gn_stats(v.x + v.y + v.z + v.w, v.x * v.x + v.y * v.y + v.z * v.z + v.w * v.w, m, inv);
    float4 gg = *(const float4*)(g + lane * 4);
    float4 bb = *(const float4*)(b + lane * 4);
    float4 f  = *(const float4*)(feat + (long long)row * 128 + lane * 4);
    float4 o;
    o.x = fmaxf((v.x - m) * inv * gg.x + bb.x + f.x, 0.f);
    o.y = fmaxf((v.y - m) * inv * gg.y + bb.y + f.y, 0.f);
    o.z = fmaxf((v.z - m) * inv * gg.z + bb.z + f.z, 0.f);
    o.w = fmaxf((v.w - m) * inv * gg.w + bb.w + f.w, 0.f);
    *(float4*)(feat + (long long)row * 128 + lane * 4) = o;
}

__global__ __launch_bounds__(256) void gn_combine_k(
    const float* __restrict__ U,
    const float* __restrict__ gU, const float* __restrict__ bU,
    const float* __restrict__ V,
    const float* __restrict__ gV, const float* __restrict__ bV,
    float* __restrict__ out, int n)
{
    int gt = blockIdx.x * blockDim.x + threadIdx.x;
    int row = gt >> 5, lane = gt & 31;
    if (row >= n) return;
    float4 u = *(const float4*)(U + (long long)row * 128 + lane * 4);
    float4 v = *(const float4*)(V + (long long)row * 128 + lane * 4);
    float mu, iu, mv, iv;
    gn_stats(u.x + u.y + u.z + u.w, u.x * u.x + u.y * u.y + u.z * u.z + u.w * u.w, mu, iu);
    gn_stats(v.x + v.y + v.z + v.w, v.x * v.x + v.y * v.y + v.z * v.z + v.w * v.w, mv, iv);
    float4 g1 = *(const float4*)(gU + lane * 4), b1 = *(const float4*)(bU + lane * 4);
    float4 g2 = *(const float4*)(gV + lane * 4), b2 = *(const float4*)(bV + lane * 4);
    float4 o;
    o.x = fmaxf((u.x - mu) * iu * g1.x + b1.x + (v.x - mv) * iv * g2.x + b2.x, 0.f);
    o.y = fmaxf((u.y - mu) * iu * g1.y + b1.y + (v.y - mv) * iv * g2.y + b2.y, 0.f);
    o.z = fmaxf((u.z - mu) * iu * g1.z + b1.z + (v.z - mv) * iv * g2.z + b2.z, 0.f);
    o.w = fmaxf((u.w - mu) * iu * g1.w + b1.w + (v.w - mv) * iv * g2.w + b2.w, 0.f);
    *(float4*)(out + (long long)row * 128 + lane * 4) = o;
}

__global__ __launch_bounds__(256) void gn_meta_k(
    const float* __restrict__ M, const float* __restrict__ nodes,
    const float* __restrict__ metaW,
    const float* __restrict__ g, const float* __restrict__ b,
    float* __restrict__ out, int n)
{
    int gt = blockIdx.x * blockDim.x + threadIdx.x;
    int row = gt >> 5, lane = gt & 31;
    if (row >= n) return;
    float4 x = *(const float4*)(M + (long long)row * 128 + lane * 4);
    float4 e = *(const float4*)(nodes + (long long)row * 8 + 4);
    int c0 = lane * 4;
    float4 w0 = *(const float4*)(metaW + (long long)(c0 + 0) * 132 + 128);
    float4 w1 = *(const float4*)(metaW + (long long)(c0 + 1) * 132 + 128);
    float4 w2 = *(const float4*)(metaW + (long long)(c0 + 2) * 132 + 128);
    float4 w3 = *(const float4*)(metaW + (long long)(c0 + 3) * 132 + 128);
    x.x += w0.x * e.x + w0.y * e.y + w0.z * e.z + w0.w * e.w;
    x.y += w1.x * e.x + w1.y * e.y + w1.z * e.z + w1.w * e.w;
    x.z += w2.x * e.x + w2.y * e.y + w2.z * e.z + w2.w * e.w;
    x.w += w3.x * e.x + w3.y * e.y + w3.z * e.z + w3.w * e.w;
    float m, inv;
    gn_stats(x.x + x.y + x.z + x.w, x.x * x.x + x.y * x.y + x.z * x.z + x.w * x.w, m, inv);
    float4 gg = *(const float4*)(g + lane * 4);
    float4 bb = *(const float4*)(b + lane * 4);
    float4 o;
    o.x = fmaxf((x.x - m) * inv * gg.x + bb.x, 0.f);
    o.y = fmaxf((x.y - m) * inv * gg.y + bb.y, 0.f);
    o.z = fmaxf((x.z - m) * inv * gg.z + bb.z, 0.f);
    o.w = fmaxf((x.w - m) * inv * gg.w + bb.w, 0.f);
    *(float4*)(out + (long long)row * 128 + lane * 4) = o;
}

__global__ __launch_bounds__(256) void lin_in_k(
    const float* __restrict__ nodes,
    const float* __restrict__ w1, const float* __restrict__ b1,
    const float* __restrict__ w2, const float* __restrict__ b2,
    float* __restrict__ h1, float* __restrict__ h2, int n)
{
    int i = blockIdx.x * blockDim.x + threadIdx.x;
    if (i >= n * 128) return;
    int node = i >> 7, c = i & 127;
    const float* xr = nodes + (long long)node * 8;
    float x0 = __ldg(xr + 0), x1 = __ldg(xr + 1), x2 = __ldg(xr + 2), x3 = __ldg(xr + 3);
    float a = fmaf(__ldg(w1 + c * 2), x0, fmaf(__ldg(w1 + c * 2 + 1), x1, __ldg(b1 + c)));
    float s = fmaf(__ldg(w2 + c * 2), x2, fmaf(__ldg(w2 + c * 2 + 1), x3, __ldg(b2 + c)));
    h1[i] = fmaxf(a, 0.f);
    h2[i] = fmaxf(s, 0.f);
}

__global__ __launch_bounds__(256) void out_copy_k(
    const float* __restrict__ feat, const float* __restrict__ nodes,
    float* __restrict__ out, int n, int tot)
{
    int i = blockIdx.x * blockDim.x + threadIdx.x;
    if (i >= tot) return;
    int nf = n * 128;
    if (i < nf) out[i] = feat[i];
    else { int j = i - nf; out[i] = nodes[(long long)(j >> 1) * 8 + (j & 1)]; }
}

// ---------------- launcher ----------------
extern "C" void kernel_launch(void* const* d_in, const int* in_sizes, int n_in,
                              void* d_out, int out_size)
{
    const float* nodes   = (const float*)d_in[0];
    const int*   idx     = (const int*)  d_in[1];
    const int*   mask    = (const int*)  d_in[2];
    const float* in1_W   = (const float*)d_in[3];
    const float* in1_b   = (const float*)d_in[4];
    const float* in2_W   = (const float*)d_in[5];
    const float* in_g    = (const float*)d_in[6];
    const float* in_bg   = (const float*)d_in[7];
    const float* seg1_W  = (const float*)d_in[8];
    const float* seg1_b  = (const float*)d_in[9];
    const float* seg2_W  = (const float*)d_in[10];
    const float* seg_g   = (const float*)d_in[11];
    const float* seg_bg  = (const float*)d_in[12];
    const float* meta_W  = (const float*)d_in[13];
    const float* meta_g  = (const float*)d_in[14];
    const float* meta_bg = (const float*)d_in[15];
    const float* ctr_W   = (const float*)d_in[16];
    const float* edge_W  = (const float*)d_in[17];
    const float* norm_g  = (const float*)d_in[18];
    const float* norm_bg = (const float*)d_in[19];
    const float* ctr2_W  = (const float*)d_in[20];
    const float* ctr2_g  = (const float*)d_in[21];
    const float* ctr2_bg = (const float*)d_in[22];
    float* out = (float*)d_out;

    const int n = in_sizes[0] / 8;    // 100000
    const int e = in_sizes[1] / 28;   // 100000

    float *feat, *h, *h2, *q, *P;
    cudaGetSymbolAddress((void**)&feat, g_feat);
    cudaGetSymbolAddress((void**)&h,    g_h);
    cudaGetSymbolAddress((void**)&h2,   g_h2);
    cudaGetSymbolAddress((void**)&q,    g_q);
    cudaGetSymbolAddress((void**)&P,    g_P);

    cudaFuncSetAttribute(gemm_tc, cudaFuncAttributeMaxDynamicSharedMemorySize, S_TOTAL);

    const int mt        = (n + 127) / 128;
    const int gn_blocks = (n * 32 + 255) / 256;

    // weights -> hi/lo bf16, padded layout (once per launch; ~4.7 MB)
    convert_w_k<<<NSLOT, 256>>>(in2_W, seg2_W, meta_W, ctr_W, ctr2_W, edge_W);

    // ---- input / seg / meta stage ----
    lin_in_k<<<(n * 128 + 255) / 256, 256>>>(nodes, in1_W, in1_b, seg1_W, seg1_b, h, h2, n);
    gemm_tc<<<dim3(mt, 2), 256, S_TOTAL>>>(h,  128, 0, q, 128, 0, n);
    gemm_tc<<<dim3(mt, 2), 256, S_TOTAL>>>(h2, 128, 1, P, 128, 0, n);  // P as N x 128 scratch
    gn_combine_k<<<gn_blocks, 256>>>(q, in_g, in_bg, P, seg_g, seg_bg, h, n);
    gemm_tc<<<dim3(mt, 2), 256, S_TOTAL>>>(h, 128, 2, q, 128, 0, n);
    gn_meta_k<<<gn_blocks, 256>>>(q, nodes, meta_W, meta_g, meta_bg, feat, n);

    // ---- 4 message-passing layers ----
    const int sc_blocks = (14 * e * 32 + 255) / 256;
    for (int i = 0; i < 4; i++) {
        gemm_tc<<<dim3(mt, 2),  256, S_TOTAL>>>(feat, 128, 3 + i,       P, LDP, 0,   n);
        gemm_tc<<<dim3(mt, 28), 256, S_TOTAL>>>(feat, 128, 11 + i * 14, P, LDP, 128, n);
        scatter_k<<<sc_blocks, 256>>>(idx, mask, P, e);
        gn_relu_k<<<gn_blocks, 256>>>(P, LDP, norm_g + i * 128, norm_bg + i * 128, h, n);
        gemm_tc<<<dim3(mt, 2), 256, S_TOTAL>>>(h, 128, 7 + i, q, 128, 0, n);
        gn_add_relu_k<<<gn_blocks, 256>>>(q, ctr2_g + i * 128, ctr2_bg + i * 128, feat, n);
    }

    int tot = n * 130;
    if (tot > out_size) tot = out_size;
    out_copy_k<<<(tot + 255) / 256, 256>>>(feat, nodes, out, n, tot);
}

// round 11
// speedup vs baseline: 1.0753x; 1.0753x over previous
#include <cuda_runtime.h>
#include <cuda_fp16.h>
#include <cstdint>

#define NN 100000
#define EE 100000
#define D  128
#define LDP 1920
#define NSLOT 67

#define WPAD   272                 // bytes per padded row (136 fp16)
#define WPLANE (128 * WPAD)        // 34816 B: one 128x128 fp16 plane
#define BPLANE (64 * WPAD)         // 17408 B: 64-row half of a weight plane

// ---------------- device scratch (no mallocs allowed) ----------------
__device__ float g_feat[NN * D];          // 51.2 MB
__device__ float g_h   [NN * D];          // 51.2 MB
__device__ float g_h2  [NN * D];          // 51.2 MB
__device__ float g_q   [NN * D];          // 51.2 MB
__device__ float g_P   [NN * LDP];        // 768 MB: [ctr(128) | 14 x edge msgs(128)]
__device__ __align__(16) unsigned char g_wb[NSLOT * WPLANE];  // 2.3 MB padded fp16 weights

// ---------------- PTX helpers (baseline ISA only) ----------------
__device__ __forceinline__ uint32_t smem_u32(const void* p) {
    uint32_t a;
    asm("{ .reg .u64 t; cvta.to.shared.u64 t, %1; cvt.u32.u64 %0, t; }" : "=r"(a) : "l"(p));
    return a;
}
#define LDSM4(r, addr) \
    asm volatile("ldmatrix.sync.aligned.m8n8.x4.shared.b16 {%0,%1,%2,%3}, [%4];" \
                 : "=r"((r)[0]), "=r"((r)[1]), "=r"((r)[2]), "=r"((r)[3]) : "r"(addr))
#define MMA_F16(d, a, b0, b1) \
    asm volatile("mma.sync.aligned.m16n8k16.row.col.f32.f16.f16.f32 " \
                 "{%0,%1,%2,%3}, {%4,%5,%6,%7}, {%8,%9}, {%0,%1,%2,%3};" \
                 : "+f"((d)[0]), "+f"((d)[1]), "+f"((d)[2]), "+f"((d)[3]) \
                 : "r"((a)[0]), "r"((a)[1]), "r"((a)[2]), "r"((a)[3]), "r"(b0), "r"(b1))

// ---------------- weight conversion: fp32 -> fp16, padded layout ----------------
// slots: 0 in2_W, 1 seg2_W, 2 meta_W[:, :128] (ld 132), 3..6 ctr_W, 7..10 ctr2_W, 11..66 edge_W
__global__ __launch_bounds__(256) void convert_w_k(
    const float* __restrict__ in2_W, const float* __restrict__ seg2_W,
    const float* __restrict__ meta_W, const float* __restrict__ ctr_W,
    const float* __restrict__ ctr2_W, const float* __restrict__ edge_W)
{
    int b = blockIdx.x;
    const float* src;
    int ld = 128;
    if      (b == 0) src = in2_W;
    else if (b == 1) src = seg2_W;
    else if (b == 2) { src = meta_W; ld = 132; }
    else if (b < 7)  src = ctr_W  + (long long)(b - 3) * 16384;
    else if (b < 11) src = ctr2_W + (long long)(b - 7) * 16384;
    else             src = edge_W + (long long)(b - 11) * 16384;
    unsigned char* base = g_wb + (size_t)b * WPLANE;
    for (int idx = threadIdx.x; idx < 16384; idx += 256) {
        int row = idx >> 7, col = idx & 127;      // row = output channel j, col = k
        float x = src[(long long)row * ld + col];
        *(__half*)(base + row * WPAD + col * 2) = __float2half_rn(x);
    }
}

// ---------------- tensor-core GEMM: C[r, coly+j] = sum_k A[r,k] * W[j,k] ----------------
// fp16 2-term (Ahi*B + Alo*B, A split hi/lo fp16, B single fp16), fp32 accum.
// 128m x 64n CTA tile, K=128 staged once, 8 warps (4m x 2n), warp tile 32x32.
// smem 87 KB -> 2 CTAs/SM. k-loop software-pipelined (double-buffered fragments).
#define S_AHI 0
#define S_ALO WPLANE
#define S_B   (2 * WPLANE)
#define S_TOTAL (2 * WPLANE + BPLANE)   // 87040 B

__global__ __launch_bounds__(256, 2)
void gemm_tc(const float* __restrict__ A, int lda, int slot0,
             float* __restrict__ C, int ldc, int coly0, int nrows)
{
    extern __shared__ char smem[];
    const uint32_t sb = smem_u32(smem);
    const int tid = threadIdx.x, lane = tid & 31, wid = tid >> 5;
    const int m0   = blockIdx.x * 128;
    const int slot = slot0 + (blockIdx.y >> 1);
    const int half = blockIdx.y & 1;
    const int coly = coly0 + blockIdx.y * 64;

    // B: copy this half's 64 rows (17 KB, L2-resident weights)
    {
        const uint4* src = (const uint4*)(g_wb + (size_t)slot * WPLANE + (size_t)half * BPLANE);
        uint4* dst = (uint4*)(smem + S_B);
        for (int i = tid; i < BPLANE / 16; i += 256) dst[i] = src[i];
    }
    // A: load fp32, split hi/lo fp16, store padded
    for (int i = tid; i < 4096; i += 256) {
        int row = i >> 5, c0 = (i & 31) * 4;
        float4 v = make_float4(0.f, 0.f, 0.f, 0.f);
        int gr = m0 + row;
        if (gr < nrows) v = *(const float4*)(A + (size_t)gr * lda + c0);
        float xs[4] = {v.x, v.y, v.z, v.w};
        uint32_t hw[2], lw[2];
#pragma unroll
        for (int j = 0; j < 2; j++) {
            __half h0 = __float2half_rn(xs[2 * j]);
            __half h1 = __float2half_rn(xs[2 * j + 1]);
            __half l0 = __float2half_rn(xs[2 * j] - __half2float(h0));
            __half l1 = __float2half_rn(xs[2 * j + 1] - __half2float(h1));
            hw[j] = (uint32_t)__half_as_ushort(h0) | ((uint32_t)__half_as_ushort(h1) << 16);
            lw[j] = (uint32_t)__half_as_ushort(l0) | ((uint32_t)__half_as_ushort(l1) << 16);
        }
        *(uint2*)(smem + S_AHI + row * WPAD + c0 * 2) = make_uint2(hw[0], hw[1]);
        *(uint2*)(smem + S_ALO + row * WPAD + c0 * 2) = make_uint2(lw[0], lw[1]);
    }
    __syncthreads();

    const int wm = (wid & 3) * 32;       // warp m offset (4 warps in m)
    const int wn = (wid >> 2) * 32;      // warp n offset (2 warps in n)
    float acc[2][4][4];
#pragma unroll
    for (int a = 0; a < 2; a++)
#pragma unroll
        for (int b = 0; b < 4; b++) { acc[a][b][0] = acc[a][b][1] = acc[a][b][2] = acc[a][b][3] = 0.f; }

    // ldmatrix lane addressing (x4): A rows m..m+15 (k0 | k0+8), B rows n..n+15 likewise
    const int arow = lane & 15, ak = (lane >> 4) * 8;
    const int brow = ((lane >> 4) << 3) + (lane & 7), bk = ((lane >> 3) & 1) * 8;

    // double-buffered fragments; prefetch k+1 before k's MMAs
    uint32_t ah[2][2][4], al[2][2][4], bb[2][2][4];

#define LOAD_FRAGS(buf, k0)                                                            \
    do {                                                                               \
        _Pragma("unroll")                                                              \
        for (int mi = 0; mi < 2; mi++) {                                               \
            uint32_t ad = sb + S_AHI + (wm + mi * 16 + arow) * WPAD + ((k0) + ak) * 2; \
            LDSM4(ah[buf][mi], ad);                                                    \
            LDSM4(al[buf][mi], ad + WPLANE);                                           \
        }                                                                              \
        _Pragma("unroll")                                                              \
        for (int np = 0; np < 2; np++) {                                               \
            uint32_t bd = sb + S_B + (wn + np * 16 + brow) * WPAD + ((k0) + bk) * 2;   \
            LDSM4(bb[buf][np], bd);                                                    \
        }                                                                              \
    } while (0)

    LOAD_FRAGS(0, 0);
#pragma unroll
    for (int ks = 0; ks < 8; ks++) {
        int cur = ks & 1;
        if (ks < 7) LOAD_FRAGS(cur ^ 1, (ks + 1) * 16);
#pragma unroll
        for (int mi = 0; mi < 2; mi++)
#pragma unroll
            for (int ni = 0; ni < 4; ni++) {
                int np = ni >> 1, hh = (ni & 1) * 2;
                MMA_F16(acc[mi][ni], ah[cur][mi], bb[cur][np][hh], bb[cur][np][hh + 1]);
                MMA_F16(acc[mi][ni], al[cur][mi], bb[cur][np][hh], bb[cur][np][hh + 1]);
            }
    }
#undef LOAD_FRAGS

    // epilogue: D frag -> gmem (float2 per thread per frag-half)
    const int r0 = lane >> 2, cq = (lane & 3) * 2;
#pragma unroll
    for (int mi = 0; mi < 2; mi++) {
        int gm = m0 + wm + mi * 16 + r0;
#pragma unroll
        for (int ni = 0; ni < 4; ni++) {
            float* cp = C + (size_t)gm * ldc + coly + wn + ni * 8 + cq;
            if (gm < nrows)     *(float2*)cp = make_float2(acc[mi][ni][0], acc[mi][ni][1]);
            if (gm + 8 < nrows) *(float2*)(cp + (size_t)8 * ldc) = make_float2(acc[mi][ni][2], acc[mi][ni][3]);
        }
    }
}

// ---------------- scatter: P[dst, 0:128] += P[src, 128 + 128*t : ...] ----------------
__global__ __launch_bounds__(256) void scatter_k(
    const int* __restrict__ idx, const int* __restrict__ mask,
    float* __restrict__ P, int ne)
{
    int gw   = (blockIdx.x * blockDim.x + threadIdx.x) >> 5;
    int lane = threadIdx.x & 31;
    if (gw >= 14 * ne) return;
    int t = gw / ne;
    int e = gw - t * ne;
    if (e >= __ldg(&mask[t])) return;
    int dst = __ldg(&idx[e * 28 + 2 * t]);
    int src = __ldg(&idx[e * 28 + 2 * t + 1]);
    float4 v = *(const float4*)(P + (long long)src * LDP + 128 + t * 128 + lane * 4);
    float* p = P + (long long)dst * LDP + lane * 4;
    asm volatile("red.global.add.v4.f32 [%0], {%1,%2,%3,%4};"
                 :: "l"(p), "f"(v.x), "f"(v.y), "f"(v.z), "f"(v.w) : "memory");
}

// ---------------- GroupNorm(1 group): 1 warp per row of 128 ----------------
__device__ __forceinline__ void gn_stats(float s1, float s2, float& mean, float& inv)
{
#pragma unroll
    for (int o = 16; o > 0; o >>= 1) {
        s1 += __shfl_xor_sync(0xffffffffu, s1, o);
        s2 += __shfl_xor_sync(0xffffffffu, s2, o);
    }
    mean = s1 * (1.f / 128.f);
    float var = s2 * (1.f / 128.f) - mean * mean;
    inv = rsqrtf(var + 1e-5f);
}

__global__ __launch_bounds__(256) void gn_relu_k(
    const float* __restrict__ X, int ldx,
    const float* __restrict__ g, const float* __restrict__ b,
    float* __restrict__ out, int n)
{
    int gt = blockIdx.x * blockDim.x + threadIdx.x;
    int row = gt >> 5, lane = gt & 31;
    if (row >= n) return;
    float4 v = *(const float4*)(X + (long long)row * ldx + lane * 4);
    float m, inv;
    gn_stats(v.x + v.y + v.z + v.w, v.x * v.x + v.y * v.y + v.z * v.z + v.w * v.w, m, inv);
    float4 gg = *(const float4*)(g + lane * 4);
    float4 bb = *(const float4*)(b + lane * 4);
    float4 o;
    o.x = fmaxf((v.x - m) * inv * gg.x + bb.x, 0.f);
    o.y = fmaxf((v.y - m) * inv * gg.y + bb.y, 0.f);
    o.z = fmaxf((v.z - m) * inv * gg.z + bb.z, 0.f);
    o.w = fmaxf((v.w - m) * inv * gg.w + bb.w, 0.f);
    *(float4*)(out + (long long)row * 128 + lane * 4) = o;
}

__global__ __launch_bounds__(256) void gn_add_relu_k(
    const float* __restrict__ Q,
    const float* __restrict__ g, const float* __restrict__ b,
    float* __restrict__ feat, int n)
{
    int gt = blockIdx.x * blockDim.x + threadIdx.x;
    int row = gt >> 5, lane = gt & 31;
    if (row >= n) return;
    float4 v = *(const float4*)(Q + (long long)row * 128 + lane * 4);
    float m, inv;
    gn_stats(v.x + v.y + v.z + v.w, v.x * v.x + v.y * v.y + v.z * v.z + v.w * v.w, m, inv);
    float4 gg = *(const float4*)(g + lane * 4);
    float4 bb = *(const float4*)(b + lane * 4);
    float4 f  = *(const float4*)(feat + (long long)row * 128 + lane * 4);
    float4 o;
    o.x = fmaxf((v.x - m) * inv * gg.x + bb.x + f.x, 0.f);
    o.y = fmaxf((v.y - m) * inv * gg.y + bb.y + f.y, 0.f);
    o.z = fmaxf((v.z - m) * inv * gg.z + bb.z + f.z, 0.f);
    o.w = fmaxf((v.w - m) * inv * gg.w + bb.w + f.w, 0.f);
    *(float4*)(feat + (long long)row * 128 + lane * 4) = o;
}

__global__ __launch_bounds__(256) void gn_combine_k(
    const float* __restrict__ U,
    const float* __restrict__ gU, const float* __restrict__ bU,
    const float* __restrict__ V,
    const float* __restrict__ gV, const float* __restrict__ bV,
    float* __restrict__ out, int n)
{
    int gt = blockIdx.x * blockDim.x + threadIdx.x;
    int row = gt >> 5, lane = gt & 31;
    if (row >= n) return;
    float4 u = *(const float4*)(U + (long long)row * 128 + lane * 4);
    float4 v = *(const float4*)(V + (long long)row * 128 + lane * 4);
    float mu, iu, mv, iv;
    gn_stats(u.x + u.y + u.z + u.w, u.x * u.x + u.y * u.y + u.z * u.z + u.w * u.w, mu, iu);
    gn_stats(v.x + v.y + v.z + v.w, v.x * v.x + v.y * v.y + v.z * v.z + v.w * v.w, mv, iv);
    float4 g1 = *(const float4*)(gU + lane * 4), b1 = *(const float4*)(bU + lane * 4);
    float4 g2 = *(const float4*)(gV + lane * 4), b2 = *(const float4*)(bV + lane * 4);
    float4 o;
    o.x = fmaxf((u.x - mu) * iu * g1.x + b1.x + (v.x - mv) * iv * g2.x + b2.x, 0.f);
    o.y = fmaxf((u.y - mu) * iu * g1.y + b1.y + (v.y - mv) * iv * g2.y + b2.y, 0.f);
    o.z = fmaxf((u.z - mu) * iu * g1.z + b1.z + (v.z - mv) * iv * g2.z + b2.z, 0.f);
    o.w = fmaxf((u.w - mu) * iu * g1.w + b1.w + (v.w - mv) * iv * g2.w + b2.w, 0.f);
    *(float4*)(out + (long long)row * 128 + lane * 4) = o;
}

__global__ __launch_bounds__(256) void gn_meta_k(
    const float* __restrict__ M, const float* __restrict__ nodes,
    const float* __restrict__ metaW,
    const float* __restrict__ g, const float* __restrict__ b,
    float* __restrict__ out, int n)
{
    int gt = blockIdx.x * blockDim.x + threadIdx.x;
    int row = gt >> 5, lane = gt & 31;
    if (row >= n) return;
    float4 x = *(const float4*)(M + (long long)row * 128 + lane * 4);
    float4 e = *(const float4*)(nodes + (long long)row * 8 + 4);
    int c0 = lane * 4;
    float4 w0 = *(const float4*)(metaW + (long long)(c0 + 0) * 132 + 128);
    float4 w1 = *(const float4*)(metaW + (long long)(c0 + 1) * 132 + 128);
    float4 w2 = *(const float4*)(metaW + (long long)(c0 + 2) * 132 + 128);
    float4 w3 = *(const float4*)(metaW + (long long)(c0 + 3) * 132 + 128);
    x.x += w0.x * e.x + w0.y * e.y + w0.z * e.z + w0.w * e.w;
    x.y += w1.x * e.x + w1.y * e.y + w1.z * e.z + w1.w * e.w;
    x.z += w2.x * e.x + w2.y * e.y + w2.z * e.z + w2.w * e.w;
    x.w += w3.x * e.x + w3.y * e.y + w3.z * e.z + w3.w * e.w;
    float m, inv;
    gn_stats(x.x + x.y + x.z + x.w, x.x * x.x + x.y * x.y + x.z * x.z + x.w * x.w, m, inv);
    float4 gg = *(const float4*)(g + lane * 4);
    float4 bb = *(const float4*)(b + lane * 4);
    float4 o;
    o.x = fmaxf((x.x - m) * inv * gg.x + bb.x, 0.f);
    o.y = fmaxf((x.y - m) * inv * gg.y + bb.y, 0.f);
    o.z = fmaxf((x.z - m) * inv * gg.z + bb.z, 0.f);
    o.w = fmaxf((x.w - m) * inv * gg.w + bb.w, 0.f);
    *(float4*)(out + (long long)row * 128 + lane * 4) = o;
}

__global__ __launch_bounds__(256) void lin_in_k(
    const float* __restrict__ nodes,
    const float* __restrict__ w1, const float* __restrict__ b1,
    const float* __restrict__ w2, const float* __restrict__ b2,
    float* __restrict__ h1, float* __restrict__ h2, int n)
{
    int i = blockIdx.x * blockDim.x + threadIdx.x;
    if (i >= n * 128) return;
    int node = i >> 7, c = i & 127;
    const float* xr = nodes + (long long)node * 8;
    float x0 = __ldg(xr + 0), x1 = __ldg(xr + 1), x2 = __ldg(xr + 2), x3 = __ldg(xr + 3);
    float a = fmaf(__ldg(w1 + c * 2), x0, fmaf(__ldg(w1 + c * 2 + 1), x1, __ldg(b1 + c)));
    float s = fmaf(__ldg(w2 + c * 2), x2, fmaf(__ldg(w2 + c * 2 + 1), x3, __ldg(b2 + c)));
    h1[i] = fmaxf(a, 0.f);
    h2[i] = fmaxf(s, 0.f);
}

__global__ __launch_bounds__(256) void out_copy_k(
    const float* __restrict__ feat, const float* __restrict__ nodes,
    float* __restrict__ out, int n, int tot)
{
    int i = blockIdx.x * blockDim.x + threadIdx.x;
    if (i >= tot) return;
    int nf = n * 128;
    if (i < nf) out[i] = feat[i];
    else { int j = i - nf; out[i] = nodes[(long long)(j >> 1) * 8 + (j & 1)]; }
}

// ---------------- launcher ----------------
extern "C" void kernel_launch(void* const* d_in, const int* in_sizes, int n_in,
                              void* d_out, int out_size)
{
    const float* nodes   = (const float*)d_in[0];
    const int*   idx     = (const int*)  d_in[1];
    const int*   mask    = (const int*)  d_in[2];
    const float* in1_W   = (const float*)d_in[3];
    const float* in1_b   = (const float*)d_in[4];
    const float* in2_W   = (const float*)d_in[5];
    const float* in_g    = (const float*)d_in[6];
    const float* in_bg   = (const float*)d_in[7];
    const float* seg1_W  = (const float*)d_in[8];
    const float* seg1_b  = (const float*)d_in[9];
    const float* seg2_W  = (const float*)d_in[10];
    const float* seg_g   = (const float*)d_in[11];
    const float* seg_bg  = (const float*)d_in[12];
    const float* meta_W  = (const float*)d_in[13];
    const float* meta_g  = (const float*)d_in[14];
    const float* meta_bg = (const float*)d_in[15];
    const float* ctr_W   = (const float*)d_in[16];
    const float* edge_W  = (const float*)d_in[17];
    const float* norm_g  = (const float*)d_in[18];
    const float* norm_bg = (const float*)d_in[19];
    const float* ctr2_W  = (const float*)d_in[20];
    const float* ctr2_g  = (const float*)d_in[21];
    const float* ctr2_bg = (const float*)d_in[22];
    float* out = (float*)d_out;

    const int n = in_sizes[0] / 8;    // 100000
    const int e = in_sizes[1] / 28;   // 100000

    float *feat, *h, *h2, *q, *P;
    cudaGetSymbolAddress((void**)&feat, g_feat);
    cudaGetSymbolAddress((void**)&h,    g_h);
    cudaGetSymbolAddress((void**)&h2,   g_h2);
    cudaGetSymbolAddress((void**)&q,    g_q);
    cudaGetSymbolAddress((void**)&P,    g_P);

    cudaFuncSetAttribute(gemm_tc, cudaFuncAttributeMaxDynamicSharedMemorySize, S_TOTAL);

    const int mt        = (n + 127) / 128;
    const int gn_blocks = (n * 32 + 255) / 256;

    // weights -> fp16, padded layout (once per launch; ~2.3 MB)
    convert_w_k<<<NSLOT, 256>>>(in2_W, seg2_W, meta_W, ctr_W, ctr2_W, edge_W);

    // ---- input / seg / meta stage ----
    lin_in_k<<<(n * 128 + 255) / 256, 256>>>(nodes, in1_W, in1_b, seg1_W, seg1_b, h, h2, n);
    gemm_tc<<<dim3(mt, 2), 256, S_TOTAL>>>(h,  128, 0, q, 128, 0, n);
    gemm_tc<<<dim3(mt, 2), 256, S_TOTAL>>>(h2, 128, 1, P, 128, 0, n);  // P as N x 128 scratch
    gn_combine_k<<<gn_blocks, 256>>>(q, in_g, in_bg, P, seg_g, seg_bg, h, n);
    gemm_tc<<<dim3(mt, 2), 256, S_TOTAL>>>(h, 128, 2, q, 128, 0, n);
    gn_meta_k<<<gn_blocks, 256>>>(q, nodes, meta_W, meta_g, meta_bg, feat, n);

    // ---- 4 message-passing layers ----
    const int sc_blocks = (14 * e * 32 + 255) / 256;
    for (int i = 0; i < 4; i++) {
        gemm_tc<<<dim3(mt, 2),  256, S_TOTAL>>>(feat, 128, 3 + i,       P, LDP, 0,   n);
        gemm_tc<<<dim3(mt, 28), 256, S_TOTAL>>>(feat, 128, 11 + i * 14, P, LDP, 128, n);
        scatter_k<<<sc_blocks, 256>>>(idx, mask, P, e);
        gn_relu_k<<<gn_blocks, 256>>>(P, LDP, norm_g + i * 128, norm_bg + i * 128, h, n);
        gemm_tc<<<dim3(mt, 2), 256, S_TOTAL>>>(h, 128, 7 + i, q, 128, 0, n);
        gn_add_relu_k<<<gn_blocks, 256>>>(q, ctr2_g + i * 128, ctr2_bg + i * 128, feat, n);
    }

    int tot = n * 130;
    if (tot > out_size) tot = out_size;
    out_copy_k<<<(tot + 255) / 256, 256>>>(feat, nodes, out, n, tot);
}

// round 14
// speedup vs baseline: 1.9548x; 1.8178x over previous
#include <cuda_runtime.h>
#include <cuda_fp16.h>
#include <cstdint>

#define NN 100000
#define EE 100000
#define D  128
#define LDP 1920
#define NSLOT 67

#define WPAD   272                 // bytes per padded row (136 fp16)
#define WPLANE (128 * WPAD)        // 34816 B: one 128x128 fp16 plane
#define BPLANE (64 * WPAD)         // 17408 B: 64-row half of a weight plane

// ---------------- device scratch (no mallocs allowed) ----------------
__device__ float g_feat[NN * D];          // 51.2 MB
__device__ float g_h   [NN * D];          // 51.2 MB
__device__ float g_h2  [NN * D];          // 51.2 MB
__device__ float g_q   [NN * D];          // 51.2 MB
__device__ float g_P   [NN * LDP];        // 768 MB: [ctr(128) | 14 x edge msgs(128)]
__device__ __align__(16) unsigned char g_wb[NSLOT * WPLANE];  // 2.3 MB padded fp16 weights

// ---------------- PTX helpers (baseline ISA only) ----------------
__device__ __forceinline__ uint32_t smem_u32(const void* p) {
    uint32_t a;
    asm("{ .reg .u64 t; cvta.to.shared.u64 t, %1; cvt.u32.u64 %0, t; }" : "=r"(a) : "l"(p));
    return a;
}
#define LDSM4(r, addr) \
    asm volatile("ldmatrix.sync.aligned.m8n8.x4.shared.b16 {%0,%1,%2,%3}, [%4];" \
                 : "=r"((r)[0]), "=r"((r)[1]), "=r"((r)[2]), "=r"((r)[3]) : "r"(addr))
#define MMA_F16(d, a, b0, b1) \
    asm volatile("mma.sync.aligned.m16n8k16.row.col.f32.f16.f16.f32 " \
                 "{%0,%1,%2,%3}, {%4,%5,%6,%7}, {%8,%9}, {%0,%1,%2,%3};" \
                 : "+f"((d)[0]), "+f"((d)[1]), "+f"((d)[2]), "+f"((d)[3]) \
                 : "r"((a)[0]), "r"((a)[1]), "r"((a)[2]), "r"((a)[3]), "r"(b0), "r"(b1))
#define CP_ASYNC16(dst, src) \
    asm volatile("cp.async.cg.shared.global [%0], [%1], 16;" :: "r"(dst), "l"(src))
#define CP_COMMIT() asm volatile("cp.async.commit_group;" ::: "memory")
#define CP_WAIT0()  asm volatile("cp.async.wait_group 0;" ::: "memory")
#define CP_WAIT1()  asm volatile("cp.async.wait_group 1;" ::: "memory")

// ---------------- weight conversion: fp32 -> fp16, padded layout ----------------
// slots: 0 in2_W, 1 seg2_W, 2 meta_W[:, :128] (ld 132), 3..6 ctr_W, 7..10 ctr2_W, 11..66 edge_W
__global__ __launch_bounds__(256) void convert_w_k(
    const float* __restrict__ in2_W, const float* __restrict__ seg2_W,
    const float* __restrict__ meta_W, const float* __restrict__ ctr_W,
    const float* __restrict__ ctr2_W, const float* __restrict__ edge_W)
{
    int b = blockIdx.x;
    const float* src;
    int ld = 128;
    if      (b == 0) src = in2_W;
    else if (b == 1) src = seg2_W;
    else if (b == 2) { src = meta_W; ld = 132; }
    else if (b < 7)  src = ctr_W  + (long long)(b - 3) * 16384;
    else if (b < 11) src = ctr2_W + (long long)(b - 7) * 16384;
    else             src = edge_W + (long long)(b - 11) * 16384;
    unsigned char* base = g_wb + (size_t)b * WPLANE;
    for (int idx = threadIdx.x; idx < 16384; idx += 256) {
        int row = idx >> 7, col = idx & 127;      // row = output channel j, col = k
        float x = src[(long long)row * ld + col];
        *(__half*)(base + row * WPAD + col * 2) = __float2half_rn(x);
    }
}

// ---------------- tensor-core GEMM, A staged once, loop over ny B-half-tiles ----------
// C[r, y*64 + j] = sum_k A[r,k] * W_slot(y)[64*(y&1)+j, k], fp32 accum,
// fp16 2-term (A split hi/lo). slot(y) = y<2 ? slotA : slotB + (y-2)/2.
// 128m x 64n per iteration, 8 warps (4m x 2n). B double-buffered via cp.async.
// smem = A hi/lo (70 KB) + 2 x B (34 KB) = 104 KB -> 2 CTAs/SM.
#define S_AHI 0
#define S_ALO WPLANE
#define S_B0  (2 * WPLANE)
#define S_TOTAL (2 * WPLANE + 2 * BPLANE)   // 104448 B

__device__ __forceinline__ void prefetch_B(uint32_t dst, const unsigned char* src, int tid)
{
    for (int i = tid; i < BPLANE / 16; i += 256)
        CP_ASYNC16(dst + i * 16, src + i * 16);
    CP_COMMIT();
}

__global__ __launch_bounds__(256, 2)
void gemm_tc(const float* __restrict__ A, int lda, int slotA, int slotB,
             float* __restrict__ C, int ldc, int ny, int nrows)
{
    extern __shared__ char smem[];
    const uint32_t sb = smem_u32(smem);
    const int tid = threadIdx.x, lane = tid & 31, wid = tid >> 5;
    const int m0 = blockIdx.x * 128;

    // kick off B prefetch for y=0 into buffer 0 (overlaps A staging)
    prefetch_B(sb + S_B0, g_wb + (size_t)slotA * WPLANE, tid);

    // A: load fp32, split hi/lo fp16, store padded (once per CTA)
    for (int i = tid; i < 4096; i += 256) {
        int row = i >> 5, c0 = (i & 31) * 4;
        float4 v = make_float4(0.f, 0.f, 0.f, 0.f);
        int gr = m0 + row;
        if (gr < nrows) v = *(const float4*)(A + (size_t)gr * lda + c0);
        float xs[4] = {v.x, v.y, v.z, v.w};
        uint32_t hw[2], lw[2];
#pragma unroll
        for (int j = 0; j < 2; j++) {
            __half h0 = __float2half_rn(xs[2 * j]);
            __half h1 = __float2half_rn(xs[2 * j + 1]);
            __half l0 = __float2half_rn(xs[2 * j] - __half2float(h0));
            __half l1 = __float2half_rn(xs[2 * j + 1] - __half2float(h1));
            hw[j] = (uint32_t)__half_as_ushort(h0) | ((uint32_t)__half_as_ushort(h1) << 16);
            lw[j] = (uint32_t)__half_as_ushort(l0) | ((uint32_t)__half_as_ushort(l1) << 16);
        }
        *(uint2*)(smem + S_AHI + row * WPAD + c0 * 2) = make_uint2(hw[0], hw[1]);
        *(uint2*)(smem + S_ALO + row * WPAD + c0 * 2) = make_uint2(lw[0], lw[1]);
    }

    const int wm = (wid & 3) * 32;       // warp m offset (4 warps in m)
    const int wn = (wid >> 2) * 32;      // warp n offset (2 warps in n)
    const int arow = lane & 15, ak = (lane >> 4) * 8;
    const int brow = ((lane >> 4) << 3) + (lane & 7), bk = ((lane >> 3) & 1) * 8;
    const int r0 = lane >> 2, cq = (lane & 3) * 2;

    for (int y = 0; y < ny; y++) {
        // prefetch next B half-tile into buffer (y+1)&1
        if (y + 1 < ny) {
            int yn = y + 1;
            int slot_n = (yn < 2) ? slotA : slotB + ((yn - 2) >> 1);
            const unsigned char* src =
                g_wb + (size_t)slot_n * WPLANE + (size_t)(yn & 1) * BPLANE;
            prefetch_B(sb + S_B0 + (uint32_t)(yn & 1) * BPLANE, src, tid);
        }
        if (y + 1 < ny) CP_WAIT1(); else CP_WAIT0();
        __syncthreads();

        const uint32_t bbase = sb + S_B0 + (uint32_t)(y & 1) * BPLANE;

        float acc[2][4][4];
#pragma unroll
        for (int a = 0; a < 2; a++)
#pragma unroll
            for (int b = 0; b < 4; b++) { acc[a][b][0] = acc[a][b][1] = acc[a][b][2] = acc[a][b][3] = 0.f; }

#pragma unroll
        for (int ks = 0; ks < 8; ks++) {
            int k0 = ks * 16;
            uint32_t ah[2][4], al[2][4], bb[2][4];
#pragma unroll
            for (int mi = 0; mi < 2; mi++) {
                uint32_t ad = sb + S_AHI + (wm + mi * 16 + arow) * WPAD + (k0 + ak) * 2;
                LDSM4(ah[mi], ad);
                LDSM4(al[mi], ad + WPLANE);
            }
#pragma unroll
            for (int np = 0; np < 2; np++) {
                uint32_t bd = bbase + (wn + np * 16 + brow) * WPAD + (k0 + bk) * 2;
                LDSM4(bb[np], bd);
            }
#pragma unroll
            for (int mi = 0; mi < 2; mi++)
#pragma unroll
                for (int ni = 0; ni < 4; ni++) {
                    int np = ni >> 1, hh = (ni & 1) * 2;
                    MMA_F16(acc[mi][ni], ah[mi], bb[np][hh], bb[np][hh + 1]);
                    MMA_F16(acc[mi][ni], al[mi], bb[np][hh], bb[np][hh + 1]);
                }
        }

        // epilogue for this y
        int coly = y * 64;
#pragma unroll
        for (int mi = 0; mi < 2; mi++) {
            int gm = m0 + wm + mi * 16 + r0;
#pragma unroll
            for (int ni = 0; ni < 4; ni++) {
                float* cp = C + (size_t)gm * ldc + coly + wn + ni * 8 + cq;
                if (gm < nrows)     *(float2*)cp = make_float2(acc[mi][ni][0], acc[mi][ni][1]);
                if (gm + 8 < nrows) *(float2*)(cp + (size_t)8 * ldc) = make_float2(acc[mi][ni][2], acc[mi][ni][3]);
            }
        }
        __syncthreads();   // all warps done reading buf (y&1) before next prefetch reuses it
    }
}

// ---------------- scatter: P[dst, 0:128] += P[src, 128 + 128*t : ...] ----------------
__global__ __launch_bounds__(256) void scatter_k(
    const int* __restrict__ idx, const int* __restrict__ mask,
    float* __restrict__ P, int ne)
{
    int gw   = (blockIdx.x * blockDim.x + threadIdx.x) >> 5;
    int lane = threadIdx.x & 31;
    if (gw >= 14 * ne) return;
    int t = gw / ne;
    int e = gw - t * ne;
    if (e >= __ldg(&mask[t])) return;
    int dst = __ldg(&idx[e * 28 + 2 * t]);
    int src = __ldg(&idx[e * 28 + 2 * t + 1]);
    float4 v = *(const float4*)(P + (long long)src * LDP + 128 + t * 128 + lane * 4);
    float* p = P + (long long)dst * LDP + lane * 4;
    asm volatile("red.global.add.v4.f32 [%0], {%1,%2,%3,%4};"
                 :: "l"(p), "f"(v.x), "f"(v.y), "f"(v.z), "f"(v.w) : "memory");
}

// ---------------- GroupNorm(1 group): 1 warp per row of 128 ----------------
__device__ __forceinline__ void gn_stats(float s1, float s2, float& mean, float& inv)
{
#pragma unroll
    for (int o = 16; o > 0; o >>= 1) {
        s1 += __shfl_xor_sync(0xffffffffu, s1, o);
        s2 += __shfl_xor_sync(0xffffffffu, s2, o);
    }
    mean = s1 * (1.f / 128.f);
    float var = s2 * (1.f / 128.f) - mean * mean;
    inv = rsqrtf(var + 1e-5f);
}

__global__ __launch_bounds__(256) void gn_relu_k(
    const float* __restrict__ X, int ldx,
    const float* __restrict__ g, const float* __restrict__ b,
    float* __restrict__ out, int n)
{
    int gt = blockIdx.x * blockDim.x + threadIdx.x;
    int row = gt >> 5, lane = gt & 31;
    if (row >= n) return;
    float4 v = *(const float4*)(X + (long long)row * ldx + lane * 4);
    float m, inv;
    gn_stats(v.x + v.y + v.z + v.w, v.x * v.x + v.y * v.y + v.z * v.z + v.w * v.w, m, inv);
    float4 gg = *(const float4*)(g + lane * 4);
    float4 bb = *(const float4*)(b + lane * 4);
    float4 o;
    o.x = fmaxf((v.x - m) * inv * gg.x + bb.x, 0.f);
    o.y = fmaxf((v.y - m) * inv * gg.y + bb.y, 0.f);
    o.z = fmaxf((v.z - m) * inv * gg.z + bb.z, 0.f);
    o.w = fmaxf((v.w - m) * inv * gg.w + bb.w, 0.f);
    *(float4*)(out + (long long)row * 128 + lane * 4) = o;
}

__global__ __launch_bounds__(256) void gn_add_relu_k(
    const float* __restrict__ Q,
    const float* __restrict__ g, const float* __restrict__ b,
    float* __restrict__ feat, int n)
{
    int gt = blockIdx.x * blockDim.x + threadIdx.x;
    int row = gt >> 5, lane = gt & 31;
    if (row >= n) return;
    float4 v = *(const float4*)(Q + (long long)row * 128 + lane * 4);
    float m, inv;
    gn_stats(v.x + v.y + v.z + v.w, v.x * v.x + v.y * v.y + v.z * v.z + v.w * v.w, m, inv);
    float4 gg = *(const float4*)(g + lane * 4);
    float4 bb = *(const float4*)(b + lane * 4);
    float4 f  = *(const float4*)(feat + (long long)row * 128 + lane * 4);
    float4 o;
    o.x = fmaxf((v.x - m) * inv * gg.x + bb.x + f.x, 0.f);
    o.y = fmaxf((v.y - m) * inv * gg.y + bb.y + f.y, 0.f);
    o.z = fmaxf((v.z - m) * inv * gg.z + bb.z + f.z, 0.f);
    o.w = fmaxf((v.w - m) * inv * gg.w + bb.w + f.w, 0.f);
    *(float4*)(feat + (long long)row * 128 + lane * 4) = o;
}

__global__ __launch_bounds__(256) void gn_combine_k(
    const float* __restrict__ U,
    const float* __restrict__ gU, const float* __restrict__ bU,
    const float* __restrict__ V,
    const float* __restrict__ gV, const float* __restrict__ bV,
    float* __restrict__ out, int n)
{
    int gt = blockIdx.x * blockDim.x + threadIdx.x;
    int row = gt >> 5, lane = gt & 31;
    if (row >= n) return;
    float4 u = *(const float4*)(U + (long long)row * 128 + lane * 4);
    float4 v = *(const float4*)(V + (long long)row * 128 + lane * 4);
    float mu, iu, mv, iv;
    gn_stats(u.x + u.y + u.z + u.w, u.x * u.x + u.y * u.y + u.z * u.z + u.w * u.w, mu, iu);
    gn_stats(v.x + v.y + v.z + v.w, v.x * v.x + v.y * v.y + v.z * v.z + v.w * v.w, mv, iv);
    float4 g1 = *(const float4*)(gU + lane * 4), b1 = *(const float4*)(bU + lane * 4);
    float4 g2 = *(const float4*)(gV + lane * 4), b2 = *(const float4*)(bV + lane * 4);
    float4 o;
    o.x = fmaxf((u.x - mu) * iu * g1.x + b1.x + (v.x - mv) * iv * g2.x + b2.x, 0.f);
    o.y = fmaxf((u.y - mu) * iu * g1.y + b1.y + (v.y - mv) * iv * g2.y + b2.y, 0.f);
    o.z = fmaxf((u.z - mu) * iu * g1.z + b1.z + (v.z - mv) * iv * g2.z + b2.z, 0.f);
    o.w = fmaxf((u.w - mu) * iu * g1.w + b1.w + (v.w - mv) * iv * g2.w + b2.w, 0.f);
    *(float4*)(out + (long long)row * 128 + lane * 4) = o;
}

__global__ __launch_bounds__(256) void gn_meta_k(
    const float* __restrict__ M, const float* __restrict__ nodes,
    const float* __restrict__ metaW,
    const float* __restrict__ g, const float* __restrict__ b,
    float* __restrict__ out, int n)
{
    int gt = blockIdx.x * blockDim.x + threadIdx.x;
    int row = gt >> 5, lane = gt & 31;
    if (row >= n) return;
    float4 x = *(const float4*)(M + (long long)row * 128 + lane * 4);
    float4 e = *(const float4*)(nodes + (long long)row * 8 + 4);
    int c0 = lane * 4;
    float4 w0 = *(const float4*)(metaW + (long long)(c0 + 0) * 132 + 128);
    float4 w1 = *(const float4*)(metaW + (long long)(c0 + 1) * 132 + 128);
    float4 w2 = *(const float4*)(metaW + (long long)(c0 + 2) * 132 + 128);
    float4 w3 = *(const float4*)(metaW + (long long)(c0 + 3) * 132 + 128);
    x.x += w0.x * e.x + w0.y * e.y + w0.z * e.z + w0.w * e.w;
    x.y += w1.x * e.x + w1.y * e.y + w1.z * e.z + w1.w * e.w;
    x.z += w2.x * e.x + w2.y * e.y + w2.z * e.z + w2.w * e.w;
    x.w += w3.x * e.x + w3.y * e.y + w3.z * e.z + w3.w * e.w;
    float m, inv;
    gn_stats(x.x + x.y + x.z + x.w, x.x * x.x + x.y * x.y + x.z * x.z + x.w * x.w, m, inv);
    float4 gg = *(const float4*)(g + lane * 4);
    float4 bb = *(const float4*)(b + lane * 4);
    float4 o;
    o.x = fmaxf((x.x - m) * inv * gg.x + bb.x, 0.f);
    o.y = fmaxf((x.y - m) * inv * gg.y + bb.y, 0.f);
    o.z = fmaxf((x.z - m) * inv * gg.z + bb.z, 0.f);
    o.w = fmaxf((x.w - m) * inv * gg.w + bb.w, 0.f);
    *(float4*)(out + (long long)row * 128 + lane * 4) = o;
}

__global__ __launch_bounds__(256) void lin_in_k(
    const float* __restrict__ nodes,
    const float* __restrict__ w1, const float* __restrict__ b1,
    const float* __restrict__ w2, const float* __restrict__ b2,
    float* __restrict__ h1, float* __restrict__ h2, int n)
{
    int i = blockIdx.x * blockDim.x + threadIdx.x;
    if (i >= n * 128) return;
    int node = i >> 7, c = i & 127;
    const float* xr = nodes + (long long)node * 8;
    float x0 = __ldg(xr + 0), x1 = __ldg(xr + 1), x2 = __ldg(xr + 2), x3 = __ldg(xr + 3);
    float a = fmaf(__ldg(w1 + c * 2), x0, fmaf(__ldg(w1 + c * 2 + 1), x1, __ldg(b1 + c)));
    float s = fmaf(__ldg(w2 + c * 2), x2, fmaf(__ldg(w2 + c * 2 + 1), x3, __ldg(b2 + c)));
    h1[i] = fmaxf(a, 0.f);
    h2[i] = fmaxf(s, 0.f);
}

__global__ __launch_bounds__(256) void out_copy_k(
    const float* __restrict__ feat, const float* __restrict__ nodes,
    float* __restrict__ out, int n, int tot)
{
    int i = blockIdx.x * blockDim.x + threadIdx.x;
    if (i >= tot) return;
    int nf = n * 128;
    if (i < nf) out[i] = feat[i];
    else { int j = i - nf; out[i] = nodes[(long long)(j >> 1) * 8 + (j & 1)]; }
}

// ---------------- launcher ----------------
extern "C" void kernel_launch(void* const* d_in, const int* in_sizes, int n_in,
                              void* d_out, int out_size)
{
    const float* nodes   = (const float*)d_in[0];
    const int*   idx     = (const int*)  d_in[1];
    const int*   mask    = (const int*)  d_in[2];
    const float* in1_W   = (const float*)d_in[3];
    const float* in1_b   = (const float*)d_in[4];
    const float* in2_W   = (const float*)d_in[5];
    const float* in_g    = (const float*)d_in[6];
    const float* in_bg   = (const float*)d_in[7];
    const float* seg1_W  = (const float*)d_in[8];
    const float* seg1_b  = (const float*)d_in[9];
    const float* seg2_W  = (const float*)d_in[10];
    const float* seg_g   = (const float*)d_in[11];
    const float* seg_bg  = (const float*)d_in[12];
    const float* meta_W  = (const float*)d_in[13];
    const float* meta_g  = (const float*)d_in[14];
    const float* meta_bg = (const float*)d_in[15];
    const float* ctr_W   = (const float*)d_in[16];
    const float* edge_W  = (const float*)d_in[17];
    const float* norm_g  = (const float*)d_in[18];
    const float* norm_bg = (const float*)d_in[19];
    const float* ctr2_W  = (const float*)d_in[20];
    const float* ctr2_g  = (const float*)d_in[21];
    const float* ctr2_bg = (const float*)d_in[22];
    float* out = (float*)d_out;

    const int n = in_sizes[0] / 8;    // 100000
    const int e = in_sizes[1] / 28;   // 100000

    float *feat, *h, *h2, *q, *P;
    cudaGetSymbolAddress((void**)&feat, g_feat);
    cudaGetSymbolAddress((void**)&h,    g_h);
    cudaGetSymbolAddress((void**)&h2,   g_h2);
    cudaGetSymbolAddress((void**)&q,    g_q);
    cudaGetSymbolAddress((void**)&P,    g_P);

    cudaFuncSetAttribute(gemm_tc, cudaFuncAttributeMaxDynamicSharedMemorySize, S_TOTAL);

    const int mt        = (n + 127) / 128;
    const int gn_blocks = (n * 32 + 255) / 256;

    // weights -> fp16, padded layout (once per launch; ~2.3 MB)
    convert_w_k<<<NSLOT, 256>>>(in2_W, seg2_W, meta_W, ctr_W, ctr2_W, edge_W);

    // ---- input / seg / meta stage ----
    lin_in_k<<<(n * 128 + 255) / 256, 256>>>(nodes, in1_W, in1_b, seg1_W, seg1_b, h, h2, n);
    gemm_tc<<<mt, 256, S_TOTAL>>>(h,  128, 0, 0, q, 128, 2, n);
    gemm_tc<<<mt, 256, S_TOTAL>>>(h2, 128, 1, 0, P, 128, 2, n);  // P as N x 128 scratch
    gn_combine_k<<<gn_blocks, 256>>>(q, in_g, in_bg, P, seg_g, seg_bg, h, n);
    gemm_tc<<<mt, 256, S_TOTAL>>>(h, 128, 2, 0, q, 128, 2, n);
    gn_meta_k<<<gn_blocks, 256>>>(q, nodes, meta_W, meta_g, meta_bg, feat, n);

    // ---- 4 message-passing layers ----
    const int sc_blocks = (14 * e * 32 + 255) / 256;
    for (int i = 0; i < 4; i++) {
        // fused: ctr (y=0,1) + 14 edge matrices (y=2..29), A=feat staged once per CTA
        gemm_tc<<<mt, 256, S_TOTAL>>>(feat, 128, 3 + i, 11 + i * 14, P, LDP, 30, n);
        scatter_k<<<sc_blocks, 256>>>(idx, mask, P, e);
        gn_relu_k<<<gn_blocks, 256>>>(P, LDP, norm_g + i * 128, norm_bg + i * 128, h, n);
        gemm_tc<<<mt, 256, S_TOTAL>>>(h, 128, 7 + i, 0, q, 128, 2, n);
        gn_add_relu_k<<<gn_blocks, 256>>>(q, ctr2_g + i * 128, ctr2_bg + i * 128, feat, n);
    }

    int tot = n * 130;
    if (tot > out_size) tot = out_size;
    out_copy_k<<<(tot + 255) / 256, 256>>>(feat, nodes, out, n, tot);
}

// round 17
// speedup vs baseline: 2.0893x; 1.0688x over previous
#include <cuda_runtime.h>
#include <cuda_fp16.h>
#include <cstdint>

#define NN 100000
#define EE 100000
#define D  128
#define MROW 1792                  // 14*128 message cols per node
#define NSLOT 67

#define WPAD   272                 // bytes per padded row (136 fp16)
#define WPLANE (128 * WPAD)        // 34816 B: one 128x128 fp16 plane
#define BPLANE (64 * WPAD)         // 17408 B: 64-row half of a weight plane

// ---------------- device scratch (no mallocs allowed) ----------------
__device__ float  g_feat[NN * D];         // 51.2 MB
__device__ float  g_h   [NN * D];         // 51.2 MB
__device__ float  g_h2  [NN * D];         // 51.2 MB
__device__ float  g_q   [NN * D];         // 51.2 MB
__device__ float  g_P32 [NN * D];         // 51.2 MB accumulator (ctr + gathered msgs)
__device__ __half g_M16 [(size_t)NN * MROW];  // 358 MB fp16 messages
__device__ int    g_cnt [NN];
__device__ int    g_off [NN + 1];
__device__ int    g_cur [NN];
__device__ int    g_elist[14 * EE];       // packed (t<<17)|src, CSR by dst
__device__ __align__(16) unsigned char g_wb[NSLOT * WPLANE];  // 2.3 MB padded fp16 weights

// ---------------- PTX helpers (baseline ISA only) ----------------
__device__ __forceinline__ uint32_t smem_u32(const void* p) {
    uint32_t a;
    asm("{ .reg .u64 t; cvta.to.shared.u64 t, %1; cvt.u32.u64 %0, t; }" : "=r"(a) : "l"(p));
    return a;
}
#define LDSM4(r, addr) \
    asm volatile("ldmatrix.sync.aligned.m8n8.x4.shared.b16 {%0,%1,%2,%3}, [%4];" \
                 : "=r"((r)[0]), "=r"((r)[1]), "=r"((r)[2]), "=r"((r)[3]) : "r"(addr))
#define MMA_F16(d, a, b0, b1) \
    asm volatile("mma.sync.aligned.m16n8k16.row.col.f32.f16.f16.f32 " \
                 "{%0,%1,%2,%3}, {%4,%5,%6,%7}, {%8,%9}, {%0,%1,%2,%3};" \
                 : "+f"((d)[0]), "+f"((d)[1]), "+f"((d)[2]), "+f"((d)[3]) \
                 : "r"((a)[0]), "r"((a)[1]), "r"((a)[2]), "r"((a)[3]), "r"(b0), "r"(b1))
#define CP_ASYNC16(dst, src) \
    asm volatile("cp.async.cg.shared.global [%0], [%1], 16;" :: "r"(dst), "l"(src))
#define CP_COMMIT() asm volatile("cp.async.commit_group;" ::: "memory")
#define CP_WAIT0()  asm volatile("cp.async.wait_group 0;" ::: "memory")
#define CP_WAIT1()  asm volatile("cp.async.wait_group 1;" ::: "memory")

// ---------------- weight conversion: fp32 -> fp16, padded layout ----------------
// slots: 0 in2_W, 1 seg2_W, 2 meta_W[:, :128] (ld 132), 3..6 ctr_W, 7..10 ctr2_W, 11..66 edge_W
__global__ __launch_bounds__(256) void convert_w_k(
    const float* __restrict__ in2_W, const float* __restrict__ seg2_W,
    const float* __restrict__ meta_W, const float* __restrict__ ctr_W,
    const float* __restrict__ ctr2_W, const float* __restrict__ edge_W)
{
    int b = blockIdx.x;
    const float* src;
    int ld = 128;
    if      (b == 0) src = in2_W;
    else if (b == 1) src = seg2_W;
    else if (b == 2) { src = meta_W; ld = 132; }
    else if (b < 7)  src = ctr_W  + (long long)(b - 3) * 16384;
    else if (b < 11) src = ctr2_W + (long long)(b - 7) * 16384;
    else             src = edge_W + (long long)(b - 11) * 16384;
    unsigned char* base = g_wb + (size_t)b * WPLANE;
    for (int idx = threadIdx.x; idx < 16384; idx += 256) {
        int row = idx >> 7, col = idx & 127;
        float x = src[(long long)row * ld + col];
        *(__half*)(base + row * WPAD + col * 2) = __float2half_rn(x);
    }
}

// ---------------- CSR build (edges constant per launch; built once) ----------------
__global__ __launch_bounds__(256) void zero_cnt_k(int n)
{
    int i = blockIdx.x * blockDim.x + threadIdx.x;
    if (i < n) g_cnt[i] = 0;
}
__global__ __launch_bounds__(256) void count_k(const int* __restrict__ idx,
                                               const int* __restrict__ mask, int ne)
{
    int i = blockIdx.x * blockDim.x + threadIdx.x;
    if (i >= 14 * ne) return;
    int t = i / ne, e = i - t * ne;
    if (e >= __ldg(&mask[t])) return;
    atomicAdd(&g_cnt[__ldg(&idx[e * 28 + 2 * t])], 1);
}
__global__ __launch_bounds__(1024) void scan_k(int n)
{
    __shared__ int ssum[1024];
    const int tid = threadIdx.x;
    const int chunk = (n + 1023) / 1024;
    int lo = tid * chunk, hi = lo + chunk; if (hi > n) hi = n; if (lo > n) lo = n;
    int s = 0;
    for (int i = lo; i < hi; i++) s += g_cnt[i];
    ssum[tid] = s;
    __syncthreads();
    for (int d = 1; d < 1024; d <<= 1) {
        int v = (tid >= d) ? ssum[tid - d] : 0;
        __syncthreads();
        ssum[tid] += v;
        __syncthreads();
    }
    int run = (tid == 0) ? 0 : ssum[tid - 1];
    for (int i = lo; i < hi; i++) {
        g_off[i] = run; g_cur[i] = run;
        run += g_cnt[i];
    }
    if (tid == 1023) g_off[n] = ssum[1023];
}
__global__ __launch_bounds__(256) void fill_k(const int* __restrict__ idx,
                                              const int* __restrict__ mask, int ne)
{
    int i = blockIdx.x * blockDim.x + threadIdx.x;
    if (i >= 14 * ne) return;
    int t = i / ne, e = i - t * ne;
    if (e >= __ldg(&mask[t])) return;
    int dst = __ldg(&idx[e * 28 + 2 * t]);
    int src = __ldg(&idx[e * 28 + 2 * t + 1]);
    int pos = atomicAdd(&g_cur[dst], 1);
    g_elist[pos] = (t << 17) | src;
}

// ---------------- gather: P32[dst] += sum over incident edges of M16[src, t] --------
__global__ __launch_bounds__(256) void gather_k(int n)
{
    int gw = (blockIdx.x * blockDim.x + threadIdx.x) >> 5;
    int lane = threadIdx.x & 31;
    if (gw >= n) return;
    float4 acc = *(const float4*)(g_P32 + (size_t)gw * 128 + lane * 4);
    int s = __ldg(&g_off[gw]), e_ = __ldg(&g_off[gw + 1]);
    for (int j = s; j < e_; j++) {
        int p = __ldg(&g_elist[j]);
        int src = p & 0x1FFFF, t = p >> 17;
        const __half2* mp = (const __half2*)(g_M16 + (size_t)src * MROW + t * 128 + lane * 4);
        float2 fa = __half22float2(mp[0]);
        float2 fb = __half22float2(mp[1]);
        acc.x += fa.x; acc.y += fa.y; acc.z += fb.x; acc.w += fb.y;
    }
    *(float4*)(g_P32 + (size_t)gw * 128 + lane * 4) = acc;
}

// ---------------- tensor-core GEMM, A staged once, loop over ny B-half-tiles ----------
// y<2 -> fp32 to C32 (ldc 128, cols y*64..); y>=2 -> fp16 to g_M16[node, (y-2)/2*128 + ((y-2)&1)*64 ..]
#define S_AHI 0
#define S_ALO WPLANE
#define S_B0  (2 * WPLANE)
#define S_TOTAL (2 * WPLANE + 2 * BPLANE)   // 104448 B

__device__ __forceinline__ void prefetch_B(uint32_t dst, const unsigned char* src, int tid)
{
    for (int i = tid; i < BPLANE / 16; i += 256)
        CP_ASYNC16(dst + i * 16, src + i * 16);
    CP_COMMIT();
}

__global__ __launch_bounds__(256, 2)
void gemm_tc(const float* __restrict__ A, int lda, int slotA, int slotB,
             float* __restrict__ C32, __half* __restrict__ C16, int ny, int nrows)
{
    extern __shared__ char smem[];
    const uint32_t sb = smem_u32(smem);
    const int tid = threadIdx.x, lane = tid & 31, wid = tid >> 5;
    const int m0 = blockIdx.x * 128;

    prefetch_B(sb + S_B0, g_wb + (size_t)slotA * WPLANE, tid);

    for (int i = tid; i < 4096; i += 256) {
        int row = i >> 5, c0 = (i & 31) * 4;
        float4 v = make_float4(0.f, 0.f, 0.f, 0.f);
        int gr = m0 + row;
        if (gr < nrows) v = *(const float4*)(A + (size_t)gr * lda + c0);
        float xs[4] = {v.x, v.y, v.z, v.w};
        uint32_t hw[2], lw[2];
#pragma unroll
        for (int j = 0; j < 2; j++) {
            __half h0 = __float2half_rn(xs[2 * j]);
            __half h1 = __float2half_rn(xs[2 * j + 1]);
            __half l0 = __float2half_rn(xs[2 * j] - __half2float(h0));
            __half l1 = __float2half_rn(xs[2 * j + 1] - __half2float(h1));
            hw[j] = (uint32_t)__half_as_ushort(h0) | ((uint32_t)__half_as_ushort(h1) << 16);
            lw[j] = (uint32_t)__half_as_ushort(l0) | ((uint32_t)__half_as_ushort(l1) << 16);
        }
        *(uint2*)(smem + S_AHI + row * WPAD + c0 * 2) = make_uint2(hw[0], hw[1]);
        *(uint2*)(smem + S_ALO + row * WPAD + c0 * 2) = make_uint2(lw[0], lw[1]);
    }

    const int wm = (wid & 3) * 32;
    const int wn = (wid >> 2) * 32;
    const int arow = lane & 15, ak = (lane >> 4) * 8;
    const int brow = ((lane >> 4) << 3) + (lane & 7), bk = ((lane >> 3) & 1) * 8;
    const int r0 = lane >> 2, cq = (lane & 3) * 2;

    for (int y = 0; y < ny; y++) {
        if (y + 1 < ny) {
            int yn = y + 1;
            int slot_n = (yn < 2) ? slotA : slotB + ((yn - 2) >> 1);
            const unsigned char* src =
                g_wb + (size_t)slot_n * WPLANE + (size_t)(yn & 1) * BPLANE;
            prefetch_B(sb + S_B0 + (uint32_t)(yn & 1) * BPLANE, src, tid);
        }
        if (y + 1 < ny) CP_WAIT1(); else CP_WAIT0();
        __syncthreads();

        const uint32_t bbase = sb + S_B0 + (uint32_t)(y & 1) * BPLANE;

        float acc[2][4][4];
#pragma unroll
        for (int a = 0; a < 2; a++)
#pragma unroll
            for (int b = 0; b < 4; b++) { acc[a][b][0] = acc[a][b][1] = acc[a][b][2] = acc[a][b][3] = 0.f; }

#pragma unroll
        for (int ks = 0; ks < 8; ks++) {
            int k0 = ks * 16;
            uint32_t ah[2][4], al[2][4], bb[2][4];
#pragma unroll
            for (int mi = 0; mi < 2; mi++) {
                uint32_t ad = sb + S_AHI + (wm + mi * 16 + arow) * WPAD + (k0 + ak) * 2;
                LDSM4(ah[mi], ad);
                LDSM4(al[mi], ad + WPLANE);
            }
#pragma unroll
            for (int np = 0; np < 2; np++) {
                uint32_t bd = bbase + (wn + np * 16 + brow) * WPAD + (k0 + bk) * 2;
                LDSM4(bb[np], bd);
            }
#pragma unroll
            for (int mi = 0; mi < 2; mi++)
#pragma unroll
                for (int ni = 0; ni < 4; ni++) {
                    int np = ni >> 1, hh = (ni & 1) * 2;
                    MMA_F16(acc[mi][ni], ah[mi], bb[np][hh], bb[np][hh + 1]);
                    MMA_F16(acc[mi][ni], al[mi], bb[np][hh], bb[np][hh + 1]);
                }
        }

        if (C16 == nullptr || y < 2) {
            int coly = y * 64;
#pragma unroll
            for (int mi = 0; mi < 2; mi++) {
                int gm = m0 + wm + mi * 16 + r0;
#pragma unroll
                for (int ni = 0; ni < 4; ni++) {
                    float* cp = C32 + (size_t)gm * 128 + coly + wn + ni * 8 + cq;
                    if (gm < nrows)     *(float2*)cp = make_float2(acc[mi][ni][0], acc[mi][ni][1]);
                    if (gm + 8 < nrows) *(float2*)(cp + (size_t)8 * 128) = make_float2(acc[mi][ni][2], acc[mi][ni][3]);
                }
            }
        } else {
            int t = (y - 2) >> 1, hsel = (y - 2) & 1;
            int colbase = t * 128 + hsel * 64;
#pragma unroll
            for (int mi = 0; mi < 2; mi++) {
                int gm = m0 + wm + mi * 16 + r0;
#pragma unroll
                for (int ni = 0; ni < 4; ni++) {
                    int col = colbase + wn + ni * 8 + cq;
                    __half2 h0 = __floats2half2_rn(acc[mi][ni][0], acc[mi][ni][1]);
                    __half2 h1 = __floats2half2_rn(acc[mi][ni][2], acc[mi][ni][3]);
                    if (gm < nrows)     *(__half2*)(C16 + (size_t)gm * MROW + col) = h0;
                    if (gm + 8 < nrows) *(__half2*)(C16 + (size_t)(gm + 8) * MROW + col) = h1;
                }
            }
        }
        __syncthreads();
    }
}

// ---------------- GroupNorm(1 group): 1 warp per row of 128 ----------------
__device__ __forceinline__ void gn_stats(float s1, float s2, float& mean, float& inv)
{
#pragma unroll
    for (int o = 16; o > 0; o >>= 1) {
        s1 += __shfl_xor_sync(0xffffffffu, s1, o);
        s2 += __shfl_xor_sync(0xffffffffu, s2, o);
    }
    mean = s1 * (1.f / 128.f);
    float var = s2 * (1.f / 128.f) - mean * mean;
    inv = rsqrtf(var + 1e-5f);
}

__global__ __launch_bounds__(256) void gn_relu_k(
    const float* __restrict__ X,
    const float* __restrict__ g, const float* __restrict__ b,
    float* __restrict__ out, int n)
{
    int gt = blockIdx.x * blockDim.x + threadIdx.x;
    int row = gt >> 5, lane = gt & 31;
    if (row >= n) return;
    float4 v = *(const float4*)(X + (long long)row * 128 + lane * 4);
    float m, inv;
    gn_stats(v.x + v.y + v.z + v.w, v.x * v.x + v.y * v.y + v.z * v.z + v.w * v.w, m, inv);
    float4 gg = *(const float4*)(g + lane * 4);
    float4 bb = *(const float4*)(b + lane * 4);
    float4 o;
    o.x = fmaxf((v.x - m) * inv * gg.x + bb.x, 0.f);
    o.y = fmaxf((v.y - m) * inv * gg.y + bb.y, 0.f);
    o.z = fmaxf((v.z - m) * inv * gg.z + bb.z, 0.f);
    o.w = fmaxf((v.w - m) * inv * gg.w + bb.w, 0.f);
    *(float4*)(out + (long long)row * 128 + lane * 4) = o;
}

__global__ __launch_bounds__(256) void gn_add_relu_k(
    const float* __restrict__ Q,
    const float* __restrict__ g, const float* __restrict__ b,
    float* __restrict__ feat, int n)
{
    int gt = blockIdx.x * blockDim.x + threadIdx.x;
    int row = gt >> 5, lane = gt & 31;
    if (row >= n) return;
    float4 v = *(const float4*)(Q + (long long)row * 128 + lane * 4);
    float m, inv;
    gn_stats(v.x + v.y + v.z + v.w, v.x * v.x + v.y * v.y + v.z * v.z + v.w * v.w, m, inv);
    float4 gg = *(const float4*)(g + lane * 4);
    float4 bb = *(const float4*)(b + lane * 4);
    float4 f  = *(const float4*)(feat + (long long)row * 128 + lane * 4);
    float4 o;
    o.x = fmaxf((v.x - m) * inv * gg.x + bb.x + f.x, 0.f);
    o.y = fmaxf((v.y - m) * inv * gg.y + bb.y + f.y, 0.f);
    o.z = fmaxf((v.z - m) * inv * gg.z + bb.z + f.z, 0.f);
    o.w = fmaxf((v.w - m) * inv * gg.w + bb.w + f.w, 0.f);
    *(float4*)(feat + (long long)row * 128 + lane * 4) = o;
}

__global__ __launch_bounds__(256) void gn_combine_k(
    const float* __restrict__ U,
    const float* __restrict__ gU, const float* __restrict__ bU,
    const float* __restrict__ V,
    const float* __restrict__ gV, const float* __restrict__ bV,
    float* __restrict__ out, int n)
{
    int gt = blockIdx.x * blockDim.x + threadIdx.x;
    int row = gt >> 5, lane = gt & 31;
    if (row >= n) return;
    float4 u = *(const float4*)(U + (long long)row * 128 + lane * 4);
    float4 v = *(const float4*)(V + (long long)row * 128 + lane * 4);
    float mu, iu, mv, iv;
    gn_stats(u.x + u.y + u.z + u.w, u.x * u.x + u.y * u.y + u.z * u.z + u.w * u.w, mu, iu);
    gn_stats(v.x + v.y + v.z + v.w, v.x * v.x + v.y * v.y + v.z * v.z + v.w * v.w, mv, iv);
    float4 g1 = *(const float4*)(gU + lane * 4), b1 = *(const float4*)(bU + lane * 4);
    float4 g2 = *(const float4*)(gV + lane * 4), b2 = *(const float4*)(bV + lane * 4);
    float4 o;
    o.x = fmaxf((u.x - mu) * iu * g1.x + b1.x + (v.x - mv) * iv * g2.x + b2.x, 0.f);
    o.y = fmaxf((u.y - mu) * iu * g1.y + b1.y + (v.y - mv) * iv * g2.y + b2.y, 0.f);
    o.z = fmaxf((u.z - mu) * iu * g1.z + b1.z + (v.z - mv) * iv * g2.z + b2.z, 0.f);
    o.w = fmaxf((u.w - mu) * iu * g1.w + b1.w + (v.w - mv) * iv * g2.w + b2.w, 0.f);
    *(float4*)(out + (long long)row * 128 + lane * 4) = o;
}

__global__ __launch_bounds__(256) void gn_meta_k(
    const float* __restrict__ M, const float* __restrict__ nodes,
    const float* __restrict__ metaW,
    const float* __restrict__ g, const float* __restrict__ b,
    float* __restrict__ out, int n)
{
    int gt = blockIdx.x * blockDim.x + threadIdx.x;
    int row = gt >> 5, lane = gt & 31;
    if (row >= n) return;
    float4 x = *(const float4*)(M + (long long)row * 128 + lane * 4);
    float4 e = *(const float4*)(nodes + (long long)row * 8 + 4);
    int c0 = lane * 4;
    float4 w0 = *(const float4*)(metaW + (long long)(c0 + 0) * 132 + 128);
    float4 w1 = *(const float4*)(metaW + (long long)(c0 + 1) * 132 + 128);
    float4 w2 = *(const float4*)(metaW + (long long)(c0 + 2) * 132 + 128);
    float4 w3 = *(const float4*)(metaW + (long long)(c0 + 3) * 132 + 128);
    x.x += w0.x * e.x + w0.y * e.y + w0.z * e.z + w0.w * e.w;
    x.y += w1.x * e.x + w1.y * e.y + w1.z * e.z + w1.w * e.w;
    x.z += w2.x * e.x + w2.y * e.y + w2.z * e.z + w2.w * e.w;
    x.w += w3.x * e.x + w3.y * e.y + w3.z * e.z + w3.w * e.w;
    float m, inv;
    gn_stats(x.x + x.y + x.z + x.w, x.x * x.x + x.y * x.y + x.z * x.z + x.w * x.w, m, inv);
    float4 gg = *(const float4*)(g + lane * 4);
    float4 bb = *(const float4*)(b + lane * 4);
    float4 o;
    o.x = fmaxf((x.x - m) * inv * gg.x + bb.x, 0.f);
    o.y = fmaxf((x.y - m) * inv * gg.y + bb.y, 0.f);
    o.z = fmaxf((x.z - m) * inv * gg.z + bb.z, 0.f);
    o.w = fmaxf((x.w - m) * inv * gg.w + bb.w, 0.f);
    *(float4*)(out + (long long)row * 128 + lane * 4) = o;
}

__global__ __launch_bounds__(256) void lin_in_k(
    const float* __restrict__ nodes,
    const float* __restrict__ w1, const float* __restrict__ b1,
    const float* __restrict__ w2, const float* __restrict__ b2,
    float* __restrict__ h1, float* __restrict__ h2, int n)
{
    int i = blockIdx.x * blockDim.x + threadIdx.x;
    if (i >= n * 128) return;
    int node = i >> 7, c = i & 127;
    const float* xr = nodes + (long long)node * 8;
    float x0 = __ldg(xr + 0), x1 = __ldg(xr + 1), x2 = __ldg(xr + 2), x3 = __ldg(xr + 3);
    float a = fmaf(__ldg(w1 + c * 2), x0, fmaf(__ldg(w1 + c * 2 + 1), x1, __ldg(b1 + c)));
    float s = fmaf(__ldg(w2 + c * 2), x2, fmaf(__ldg(w2 + c * 2 + 1), x3, __ldg(b2 + c)));
    h1[i] = fmaxf(a, 0.f);
    h2[i] = fmaxf(s, 0.f);
}

__global__ __launch_bounds__(256) void out_copy_k(
    const float* __restrict__ feat, const float* __restrict__ nodes,
    float* __restrict__ out, int n, int tot)
{
    int i = blockIdx.x * blockDim.x + threadIdx.x;
    if (i >= tot) return;
    int nf = n * 128;
    if (i < nf) out[i] = feat[i];
    else { int j = i - nf; out[i] = nodes[(long long)(j >> 1) * 8 + (j & 1)]; }
}

// ---------------- launcher ----------------
extern "C" void kernel_launch(void* const* d_in, const int* in_sizes, int n_in,
                              void* d_out, int out_size)
{
    const float* nodes   = (const float*)d_in[0];
    const int*   idx     = (const int*)  d_in[1];
    const int*   mask    = (const int*)  d_in[2];
    const float* in1_W   = (const float*)d_in[3];
    const float* in1_b   = (const float*)d_in[4];
    const float* in2_W   = (const float*)d_in[5];
    const float* in_g    = (const float*)d_in[6];
    const float* in_bg   = (const float*)d_in[7];
    const float* seg1_W  = (const float*)d_in[8];
    const float* seg1_b  = (const float*)d_in[9];
    const float* seg2_W  = (const float*)d_in[10];
    const float* seg_g   = (const float*)d_in[11];
    const float* seg_bg  = (const float*)d_in[12];
    const float* meta_W  = (const float*)d_in[13];
    const float* meta_g  = (const float*)d_in[14];
    const float* meta_bg = (const float*)d_in[15];
    const float* ctr_W   = (const float*)d_in[16];
    const float* edge_W  = (const float*)d_in[17];
    const float* norm_g  = (const float*)d_in[18];
    const float* norm_bg = (const float*)d_in[19];
    const float* ctr2_W  = (const float*)d_in[20];
    const float* ctr2_g  = (const float*)d_in[21];
    const float* ctr2_bg = (const float*)d_in[22];
    float* out = (float*)d_out;

    const int n = in_sizes[0] / 8;    // 100000
    const int e = in_sizes[1] / 28;   // 100000

    float *feat, *h, *h2, *q, *P32;
    __half* M16;
    cudaGetSymbolAddress((void**)&feat, g_feat);
    cudaGetSymbolAddress((void**)&h,    g_h);
    cudaGetSymbolAddress((void**)&h2,   g_h2);
    cudaGetSymbolAddress((void**)&q,    g_q);
    cudaGetSymbolAddress((void**)&P32,  g_P32);
    cudaGetSymbolAddress((void**)&M16,  g_M16);

    cudaFuncSetAttribute(gemm_tc, cudaFuncAttributeMaxDynamicSharedMemorySize, S_TOTAL);

    const int mt        = (n + 127) / 128;
    const int gn_blocks = (n * 32 + 255) / 256;
    const int et_blocks = (14 * e + 255) / 256;

    // weights -> fp16 (once per launch)
    convert_w_k<<<NSLOT, 256>>>(in2_W, seg2_W, meta_W, ctr_W, ctr2_W, edge_W);

    // CSR by dst (edges constant; built once, used by all 4 layers)
    zero_cnt_k<<<(n + 255) / 256, 256>>>(n);
    count_k<<<et_blocks, 256>>>(idx, mask, e);
    scan_k<<<1, 1024>>>(n);
    fill_k<<<et_blocks, 256>>>(idx, mask, e);

    // ---- input / seg / meta stage ----
    lin_in_k<<<(n * 128 + 255) / 256, 256>>>(nodes, in1_W, in1_b, seg1_W, seg1_b, h, h2, n);
    gemm_tc<<<mt, 256, S_TOTAL>>>(h,  128, 0, 0, q,   nullptr, 2, n);
    gemm_tc<<<mt, 256, S_TOTAL>>>(h2, 128, 1, 0, P32, nullptr, 2, n);
    gn_combine_k<<<gn_blocks, 256>>>(q, in_g, in_bg, P32, seg_g, seg_bg, h, n);
    gemm_tc<<<mt, 256, S_TOTAL>>>(h, 128, 2, 0, q, nullptr, 2, n);
    gn_meta_k<<<gn_blocks, 256>>>(q, nodes, meta_W, meta_g, meta_bg, feat, n);

    // ---- 4 message-passing layers ----
    for (int i = 0; i < 4; i++) {
        // fused: ctr -> P32 (fp32), 14 edge matrices -> M16 (fp16); A=feat staged once
        gemm_tc<<<mt, 256, S_TOTAL>>>(feat, 128, 3 + i, 11 + i * 14, P32, M16, 30, n);
        gather_k<<<(n * 32 + 255) / 256, 256>>>(n);
        gn_relu_k<<<gn_blocks, 256>>>(P32, norm_g + i * 128, norm_bg + i * 128, h, n);
        gemm_tc<<<mt, 256, S_TOTAL>>>(h, 128, 7 + i, 0, q, nullptr, 2, n);
        gn_add_relu_k<<<gn_blocks, 256>>>(q, ctr2_g + i * 128, ctr2_bg + i * 128, feat, n);
    }

    int tot = n * 130;
    if (tot > out_size) tot = out_size;
    out_copy_k<<<(tot + 255) / 256, 256>>>(feat, nodes, out, n, tot);
}